// round 15
// baseline (speedup 1.0000x reference)
#include <cuda_runtime.h>
#include <cuda_bf16.h>
#include <math.h>

#define N_NODES   50000
#define N_EDGES   800000
#define IN_FEATS  256
#define HID       64
#define HEADS     3
#define HD        192   // HEADS*HID
#define OUT_FEATS 64
#define NEG_SLOPE 0.2f

typedef unsigned long long ull;

// ---------------- device scratch (no allocs allowed) ----------------
__device__ float g_feat[(size_t)N_NODES * HD];
__device__ float g_x[(size_t)N_NODES * HD];
__device__ float g_hid[(size_t)N_NODES * HID];
__device__ float g_el[(size_t)N_NODES * HEADS];
__device__ float g_er[(size_t)N_NODES * HEADS];
__device__ float g_m[(size_t)N_NODES * HEADS];
__device__ float g_w[(size_t)N_EDGES * 4];       // per-edge softmax numerators (padded)
__device__ int   g_rowptr[N_NODES + 1];
__device__ int   g_cnt[N_NODES];
__device__ int   g_srcs[N_EDGES];                // src ids in CSR (dst-grouped) order
__device__ int   g_edst[N_EDGES];                // dst id per CSR slot

// ---------------- CSR build ----------------
__global__ void hist_k(const int* __restrict__ dst) {
    int e = blockIdx.x * blockDim.x + threadIdx.x;
    if (e < N_EDGES) atomicAdd(&g_cnt[dst[e]], 1);
}

__global__ void scan_k() {
    __shared__ int part[1024];
    int t = threadIdx.x;
    const int chunk = (N_NODES + 1023) / 1024;
    int beg = t * chunk;
    int end = min(beg + chunk, N_NODES);
    int s = 0;
    for (int i = beg; i < end; i++) s += g_cnt[i];
    part[t] = s;
    __syncthreads();
    for (int off = 1; off < 1024; off <<= 1) {
        int v = 0;
        if (t >= off) v = part[t - off];
        __syncthreads();
        part[t] += v;
        __syncthreads();
    }
    int run = (t == 0) ? 0 : part[t - 1];
    for (int i = beg; i < end; i++) { g_rowptr[i] = run; run += g_cnt[i]; }
    if (t == 1023) g_rowptr[N_NODES] = part[1023];
}

__global__ void scatter_k(const int* __restrict__ src, const int* __restrict__ dst) {
    int e = blockIdx.x * blockDim.x + threadIdx.x;
    if (e < N_EDGES) {
        int d = dst[e];
        int pos = atomicAdd(&g_cnt[d], 1);
        int slot = g_rowptr[d] + pos;
        g_srcs[slot] = src[e];
        g_edst[slot] = d;
    }
}

// ---------------- packed-f32x2 SGEMM 128x64 tile, 4x8 microtile, 256 threads --
union U4 { float4 f; ull p[2]; };
union U2 { ull p; float2 f; };

__device__ __forceinline__ ull dupf(float a) {
    ull r;
    asm("mov.b64 %0, {%1, %1};" : "=l"(r) : "f"(a));
    return r;
}
__device__ __forceinline__ void ffma2(ull& d, ull a, ull b) {
    asm("fma.rn.f32x2 %0, %1, %2, %0;" : "+l"(d) : "l"(a), "l"(b));
}

// C[M,N] = A[M,K] @ B[K,N] (+bias)(+relu). BN=64 per blockIdx.y.
// If al != null: also write g_el/g_er for head = blockIdx.y.
template<int K>
__global__ void __launch_bounds__(256)
gemm_k(const float* __restrict__ A, const float* __restrict__ B,
       float* __restrict__ C, int M, int N,
       const float* __restrict__ bias, int act,
       const float* __restrict__ al, const float* __restrict__ ar) {
    __shared__ float As[2][16][128];   // [buf][k][m]
    __shared__ float Bs[2][16][64];    // [buf][k][n]
    const int tid = threadIdx.x;
    const int tm = tid >> 3;        // 0..31 (4 rows each)
    const int tn = tid & 7;         // 0..7  (8 cols each, split 4+4)
    const int bm = blockIdx.x * 128;
    const int bn = blockIdx.y * 64;

    ull accP[4][4];
#pragma unroll
    for (int i = 0; i < 4; i++)
#pragma unroll
        for (int j = 0; j < 4; j++) accP[i][j] = 0ull;

    // A: each thread loads 2 float4 of one row (row = tid>>1, k-half = tid&1)
    const int arow = tid >> 1;
    const int ahalf = tid & 1;
    const float* aptr = A + (size_t)(bm + arow) * K + ahalf * 8;
    const bool aok = (bm + arow) < M;
    // B: one float4 per thread
    const int bbr = tid >> 4, bc4 = (tid & 15) << 2;

    float4 av0, av1, bv;
    av0 = aok ? *(const float4*)(aptr + 0) : make_float4(0.f, 0.f, 0.f, 0.f);
    av1 = aok ? *(const float4*)(aptr + 4) : make_float4(0.f, 0.f, 0.f, 0.f);
    bv = *(const float4*)&B[(size_t)bbr * N + bn + bc4];

    const int T = K / 16;
#pragma unroll 1
    for (int t = 0; t < T; t++) {
        const int buf = t & 1;
        As[buf][ahalf * 8 + 0][arow] = av0.x;
        As[buf][ahalf * 8 + 1][arow] = av0.y;
        As[buf][ahalf * 8 + 2][arow] = av0.z;
        As[buf][ahalf * 8 + 3][arow] = av0.w;
        As[buf][ahalf * 8 + 4][arow] = av1.x;
        As[buf][ahalf * 8 + 5][arow] = av1.y;
        As[buf][ahalf * 8 + 6][arow] = av1.z;
        As[buf][ahalf * 8 + 7][arow] = av1.w;
        *(float4*)&Bs[buf][bbr][bc4] = bv;
        __syncthreads();
        if (t + 1 < T) {
            int k0 = (t + 1) * 16;
            av0 = aok ? *(const float4*)(aptr + k0 + 0) : make_float4(0.f, 0.f, 0.f, 0.f);
            av1 = aok ? *(const float4*)(aptr + k0 + 4) : make_float4(0.f, 0.f, 0.f, 0.f);
            bv = *(const float4*)&B[(size_t)(k0 + bbr) * N + bn + bc4];
        }
#pragma unroll
        for (int k = 0; k < 16; k++) {
            U4 a0, b0, b1;
            a0.f = *(const float4*)&As[buf][k][tm * 4];
            b0.f = *(const float4*)&Bs[buf][k][tn * 4];
            b1.f = *(const float4*)&Bs[buf][k][tn * 4 + 32];
            ull bp[4] = {b0.p[0], b0.p[1], b1.p[0], b1.p[1]};
            float a[4] = {a0.f.x, a0.f.y, a0.f.z, a0.f.w};
#pragma unroll
            for (int i = 0; i < 4; i++) {
                ull ad = dupf(a[i]);
#pragma unroll
                for (int jp = 0; jp < 4; jp++) ffma2(accP[i][jp], ad, bp[jp]);
            }
        }
        // single sync per iter: next store targets buf^1, whose last read was
        // iter t-1, separated by this iter's sync above.
    }

    // unpack
    float acc[4][8];
#pragma unroll
    for (int i = 0; i < 4; i++)
#pragma unroll
        for (int jp = 0; jp < 4; jp++) {
            U2 u; u.p = accP[i][jp];
            int j0 = (jp < 2) ? jp * 2 : 4 + (jp - 2) * 2;
            acc[i][j0] = u.f.x;
            acc[i][j0 + 1] = u.f.y;
        }

    // epilogue
    float elp[4], erp[4], alv[8], arv[8], bvv[8];
    const int head = blockIdx.y;
    if (al) {
#pragma unroll
        for (int j = 0; j < 8; j++) {
            int c = tn * 4 + ((j < 4) ? j : 32 + (j - 4));
            alv[j] = __ldg(&al[head * 64 + c]);
            arv[j] = __ldg(&ar[head * 64 + c]);
        }
#pragma unroll
        for (int i = 0; i < 4; i++) { elp[i] = 0.f; erp[i] = 0.f; }
    }
    if (bias) {
#pragma unroll
        for (int j = 0; j < 8; j++) {
            int c = tn * 4 + ((j < 4) ? j : 32 + (j - 4));
            bvv[j] = __ldg(&bias[bn + c]);
        }
    }
#pragma unroll
    for (int i = 0; i < 4; i++) {
        int gr = bm + tm * 4 + i;
        float v[8];
#pragma unroll
        for (int j = 0; j < 8; j++) {
            float t = acc[i][j];
            if (bias) t += bvv[j];
            if (act) t = fmaxf(t, 0.f);
            v[j] = t;
            if (al) { elp[i] += t * alv[j]; erp[i] += t * arv[j]; }
        }
        if (gr < M) {
            float* cp = C + (size_t)gr * N + bn;
            *(float4*)(cp + tn * 4)      = make_float4(v[0], v[1], v[2], v[3]);
            *(float4*)(cp + tn * 4 + 32) = make_float4(v[4], v[5], v[6], v[7]);
        }
    }
    if (al) {
#pragma unroll
        for (int off = 1; off < 8; off <<= 1) {
#pragma unroll
            for (int i = 0; i < 4; i++) {
                elp[i] += __shfl_xor_sync(0xFFFFFFFFu, elp[i], off);
                erp[i] += __shfl_xor_sync(0xFFFFFFFFu, erp[i], off);
            }
        }
        if (tn == 0) {
#pragma unroll
            for (int i = 0; i < 4; i++) {
                int gr = bm + tm * 4 + i;
                if (gr < M) {
                    g_el[gr * 3 + head] = elp[i];
                    g_er[gr * 3 + head] = erp[i];
                }
            }
        }
    }
}

__device__ __forceinline__ float leaky(float x) { return x > 0.f ? x : NEG_SLOPE * x; }

// ---------------- per-dst max (one warp per node) ----------------
__global__ void max_k() {
    int warp = (blockIdx.x * blockDim.x + threadIdx.x) >> 5;
    int lane = threadIdx.x & 31;
    if (warp >= N_NODES) return;
    int beg = g_rowptr[warp], end = g_rowptr[warp + 1];
    float er0 = g_er[warp * 3 + 0];
    float er1 = g_er[warp * 3 + 1];
    float er2 = g_er[warp * 3 + 2];
    float m0 = -1e30f, m1 = -1e30f, m2 = -1e30f;
    for (int i = beg + lane; i < end; i += 32) {
        int s = g_srcs[i];
        m0 = fmaxf(m0, leaky(g_el[s * 3 + 0] + er0));
        m1 = fmaxf(m1, leaky(g_el[s * 3 + 1] + er1));
        m2 = fmaxf(m2, leaky(g_el[s * 3 + 2] + er2));
    }
#pragma unroll
    for (int off = 16; off; off >>= 1) {
        m0 = fmaxf(m0, __shfl_xor_sync(0xFFFFFFFFu, m0, off));
        m1 = fmaxf(m1, __shfl_xor_sync(0xFFFFFFFFu, m1, off));
        m2 = fmaxf(m2, __shfl_xor_sync(0xFFFFFFFFu, m2, off));
    }
    if (lane == 0) {
        g_m[warp * 3 + 0] = m0;
        g_m[warp * 3 + 1] = m1;
        g_m[warp * 3 + 2] = m2;
    }
}

// ---------------- per-edge softmax numerators ----------------
__global__ void wgt_k() {
    int e = blockIdx.x * blockDim.x + threadIdx.x;
    if (e >= N_EDGES) return;
    int s = g_srcs[e];
    int d = g_edst[e];
    float w0 = __expf(leaky(g_el[s * 3 + 0] + g_er[d * 3 + 0]) - g_m[d * 3 + 0]);
    float w1 = __expf(leaky(g_el[s * 3 + 1] + g_er[d * 3 + 1]) - g_m[d * 3 + 1]);
    float w2 = __expf(leaky(g_el[s * 3 + 2] + g_er[d * 3 + 2]) - g_m[d * 3 + 2]);
    *(float4*)&g_w[(size_t)e * 4] = make_float4(w0, w1, w2, 0.f);
}

// ---------------- aggregation: one warp per dst node ----------------
__global__ void agg_k(const float* __restrict__ feat, const float* __restrict__ bias,
                      float* __restrict__ out) {
    int warp = (blockIdx.x * blockDim.x + threadIdx.x) >> 5;
    int lane = threadIdx.x & 31;
    if (warp >= N_NODES) return;
    int beg = g_rowptr[warp], end = g_rowptr[warp + 1];

    int base = lane * 6;
    int h0 = (base + 0) >> 6, h1 = (base + 1) >> 6, h2 = (base + 2) >> 6;
    int h3 = (base + 3) >> 6, h4 = (base + 4) >> 6, h5 = (base + 5) >> 6;
    float acc0 = 0.f, acc1 = 0.f, acc2 = 0.f, acc3 = 0.f, acc4 = 0.f, acc5 = 0.f;
    float s0 = 0.f, s1 = 0.f, s2 = 0.f;

    int sNext = 0;
    float4 wNext = make_float4(0.f, 0.f, 0.f, 0.f);
    if (beg < end) {
        sNext = g_srcs[beg];
        wNext = *(const float4*)&g_w[(size_t)beg * 4];
    }
    for (int i = beg; i < end; i++) {
        int s = sNext;
        float4 w = wNext;
        if (i + 1 < end) {
            sNext = g_srcs[i + 1];
            wNext = *(const float4*)&g_w[(size_t)(i + 1) * 4];
        }
        s0 += w.x; s1 += w.y; s2 += w.z;
        const float* fp = feat + (size_t)s * HD + base;
        float2 v0 = *(const float2*)(fp + 0);
        float2 v1 = *(const float2*)(fp + 2);
        float2 v2 = *(const float2*)(fp + 4);
        float wa0 = h0 == 0 ? w.x : (h0 == 1 ? w.y : w.z);
        float wa1 = h1 == 0 ? w.x : (h1 == 1 ? w.y : w.z);
        float wa2 = h2 == 0 ? w.x : (h2 == 1 ? w.y : w.z);
        float wa3 = h3 == 0 ? w.x : (h3 == 1 ? w.y : w.z);
        float wa4 = h4 == 0 ? w.x : (h4 == 1 ? w.y : w.z);
        float wa5 = h5 == 0 ? w.x : (h5 == 1 ? w.y : w.z);
        acc0 += wa0 * v0.x; acc1 += wa1 * v0.y;
        acc2 += wa2 * v1.x; acc3 += wa3 * v1.y;
        acc4 += wa4 * v2.x; acc5 += wa5 * v2.y;
    }
    float i0 = 0.f, i1 = 0.f, i2 = 0.f;
    if (end > beg) { i0 = 1.f / s0; i1 = 1.f / s1; i2 = 1.f / s2; }
    float ia0 = h0 == 0 ? i0 : (h0 == 1 ? i1 : i2);
    float ia1 = h1 == 0 ? i0 : (h1 == 1 ? i1 : i2);
    float ia2 = h2 == 0 ? i0 : (h2 == 1 ? i1 : i2);
    float ia3 = h3 == 0 ? i0 : (h3 == 1 ? i1 : i2);
    float ia4 = h4 == 0 ? i0 : (h4 == 1 ? i1 : i2);
    float ia5 = h5 == 0 ? i0 : (h5 == 1 ? i1 : i2);
    float* op = out + (size_t)warp * HD + base;
    op[0] = fmaxf(acc0 * ia0 + bias[base + 0], 0.f);
    op[1] = fmaxf(acc1 * ia1 + bias[base + 1], 0.f);
    op[2] = fmaxf(acc2 * ia2 + bias[base + 2], 0.f);
    op[3] = fmaxf(acc3 * ia3 + bias[base + 3], 0.f);
    op[4] = fmaxf(acc4 * ia4 + bias[base + 4], 0.f);
    op[5] = fmaxf(acc5 * ia5 + bias[base + 5], 0.f);
}

// ---------------- host launch ----------------
extern "C" void kernel_launch(void* const* d_in, const int* in_sizes, int n_in,
                              void* d_out, int out_size) {
    const float* features = (const float*)d_in[0];
    const int*   src      = (const int*)d_in[1];
    const int*   dst      = (const int*)d_in[2];
    const float* W1  = (const float*)d_in[3];
    const float* al1 = (const float*)d_in[4];
    const float* ar1 = (const float*)d_in[5];
    const float* b1  = (const float*)d_in[6];
    const float* W2  = (const float*)d_in[7];
    const float* al2 = (const float*)d_in[8];
    const float* ar2 = (const float*)d_in[9];
    const float* b2  = (const float*)d_in[10];
    const float* Wm1 = (const float*)d_in[11];
    const float* bm1 = (const float*)d_in[12];
    const float* Wm2 = (const float*)d_in[13];
    const float* bm2 = (const float*)d_in[14];
    float* out = (float*)d_out;

    float *feat, *x, *hid;
    int *cnt;
    cudaGetSymbolAddress((void**)&feat, g_feat);
    cudaGetSymbolAddress((void**)&x, g_x);
    cudaGetSymbolAddress((void**)&hid, g_hid);
    cudaGetSymbolAddress((void**)&cnt, g_cnt);

    const int EB = (N_EDGES + 255) / 256;
    const int WB = (N_NODES * 32 + 255) / 256;
    const int GM = (N_NODES + 127) / 128;

    cudaMemsetAsync(cnt, 0, N_NODES * sizeof(int));
    hist_k<<<EB, 256>>>(dst);
    scan_k<<<1, 1024>>>();
    cudaMemsetAsync(cnt, 0, N_NODES * sizeof(int));
    scatter_k<<<EB, 256>>>(src, dst);

    // ---- GAT layer 1 ----
    gemm_k<IN_FEATS><<<dim3(GM, 3), 256>>>(features, W1, feat, N_NODES, HD, nullptr, 0, al1, ar1);
    max_k<<<WB, 256>>>();
    wgt_k<<<EB, 256>>>();
    agg_k<<<WB, 256>>>(feat, b1, x);

    // ---- GAT layer 2 ----
    gemm_k<HD><<<dim3(GM, 3), 256>>>(x, W2, feat, N_NODES, HD, nullptr, 0, al2, ar2);
    max_k<<<WB, 256>>>();
    wgt_k<<<EB, 256>>>();
    agg_k<<<WB, 256>>>(feat, b2, x);

    // ---- MLP head ----
    gemm_k<HD><<<dim3(GM, 1), 256>>>(x, Wm1, hid, N_NODES, HID, bm1, 1, nullptr, nullptr);
    gemm_k<HID><<<dim3(GM, 1), 256>>>(hid, Wm2, out, N_NODES, OUT_FEATS, bm2, 0, nullptr, nullptr);
}

// round 16
// speedup vs baseline: 1.0024x; 1.0024x over previous
#include <cuda_runtime.h>
#include <cuda_bf16.h>
#include <math.h>

#define N_NODES   50000
#define N_EDGES   800000
#define IN_FEATS  256
#define HID       64
#define HEADS     3
#define HD        192   // HEADS*HID
#define OUT_FEATS 64
#define NEG_SLOPE 0.2f

typedef unsigned long long ull;

// ---------------- device scratch (no allocs allowed) ----------------
__device__ float g_feat[(size_t)N_NODES * HD];
__device__ float g_x[(size_t)N_NODES * HD];
__device__ float g_hid[(size_t)N_NODES * HID];
__device__ float g_el[(size_t)N_NODES * HEADS];
__device__ float g_er[(size_t)N_NODES * HEADS];
__device__ float g_m[(size_t)N_NODES * HEADS];
__device__ float g_w[(size_t)N_EDGES * 4];       // per-edge softmax numerators (padded)
__device__ int   g_rowptr[N_NODES + 1];
__device__ int   g_cnt[N_NODES];
__device__ int   g_srcs[N_EDGES];                // src ids in CSR (dst-grouped) order
__device__ int   g_edst[N_EDGES];                // dst id per CSR slot

// ---------------- CSR build ----------------
__global__ void hist_k(const int* __restrict__ dst) {
    int e = blockIdx.x * blockDim.x + threadIdx.x;
    if (e < N_EDGES) atomicAdd(&g_cnt[dst[e]], 1);
}

__global__ void scan_k() {
    __shared__ int part[1024];
    int t = threadIdx.x;
    const int chunk = (N_NODES + 1023) / 1024;
    int beg = t * chunk;
    int end = min(beg + chunk, N_NODES);
    int s = 0;
    for (int i = beg; i < end; i++) s += g_cnt[i];
    part[t] = s;
    __syncthreads();
    for (int off = 1; off < 1024; off <<= 1) {
        int v = 0;
        if (t >= off) v = part[t - off];
        __syncthreads();
        part[t] += v;
        __syncthreads();
    }
    int run = (t == 0) ? 0 : part[t - 1];
    for (int i = beg; i < end; i++) { g_rowptr[i] = run; run += g_cnt[i]; }
    if (t == 1023) g_rowptr[N_NODES] = part[1023];
}

__global__ void scatter_k(const int* __restrict__ src, const int* __restrict__ dst) {
    int e = blockIdx.x * blockDim.x + threadIdx.x;
    if (e < N_EDGES) {
        int d = dst[e];
        int pos = atomicAdd(&g_cnt[d], 1);
        int slot = g_rowptr[d] + pos;
        g_srcs[slot] = src[e];
        g_edst[slot] = d;
    }
}

// ---------------- packed-f32x2 SGEMM 128x64 tile, 4x8 microtile, 256 threads --
union U4 { float4 f; ull p[2]; };
union U2 { ull p; float2 f; };

__device__ __forceinline__ ull dupf(float a) {
    ull r;
    asm("mov.b64 %0, {%1, %1};" : "=l"(r) : "f"(a));
    return r;
}
__device__ __forceinline__ void ffma2(ull& d, ull a, ull b) {
    asm("fma.rn.f32x2 %0, %1, %2, %0;" : "+l"(d) : "l"(a), "l"(b));
}

// C[M,N] = A[M,K] @ B[K,N] (+bias)(+relu). BN=64 per blockIdx.y.
// If al != null: also write g_el/g_er for head = blockIdx.y.
template<int K>
__global__ void __launch_bounds__(256)
gemm_k(const float* __restrict__ A, const float* __restrict__ B,
       float* __restrict__ C, int M, int N,
       const float* __restrict__ bias, int act,
       const float* __restrict__ al, const float* __restrict__ ar) {
    __shared__ float As[2][16][128];   // [buf][k][m]
    __shared__ float Bs[2][16][64];    // [buf][k][n]
    const int tid = threadIdx.x;
    const int tm = tid >> 3;        // 0..31 (4 rows each)
    const int tn = tid & 7;         // 0..7  (8 cols each, split 4+4)
    const int bm = blockIdx.x * 128;
    const int bn = blockIdx.y * 64;

    ull accP[4][4];
#pragma unroll
    for (int i = 0; i < 4; i++)
#pragma unroll
        for (int j = 0; j < 4; j++) accP[i][j] = 0ull;

    // A: each thread loads 2 float4 of one row (row = tid>>1, k-half = tid&1)
    const int arow = tid >> 1;
    const int ahalf = tid & 1;
    const float* aptr = A + (size_t)(bm + arow) * K + ahalf * 8;
    const bool aok = (bm + arow) < M;
    // B: one float4 per thread
    const int bbr = tid >> 4, bc4 = (tid & 15) << 2;

    float4 av0, av1, bv;
    av0 = aok ? *(const float4*)(aptr + 0) : make_float4(0.f, 0.f, 0.f, 0.f);
    av1 = aok ? *(const float4*)(aptr + 4) : make_float4(0.f, 0.f, 0.f, 0.f);
    bv = *(const float4*)&B[(size_t)bbr * N + bn + bc4];

    const int T = K / 16;
#pragma unroll 1
    for (int t = 0; t < T; t++) {
        const int buf = t & 1;
        As[buf][ahalf * 8 + 0][arow] = av0.x;
        As[buf][ahalf * 8 + 1][arow] = av0.y;
        As[buf][ahalf * 8 + 2][arow] = av0.z;
        As[buf][ahalf * 8 + 3][arow] = av0.w;
        As[buf][ahalf * 8 + 4][arow] = av1.x;
        As[buf][ahalf * 8 + 5][arow] = av1.y;
        As[buf][ahalf * 8 + 6][arow] = av1.z;
        As[buf][ahalf * 8 + 7][arow] = av1.w;
        *(float4*)&Bs[buf][bbr][bc4] = bv;
        __syncthreads();
        if (t + 1 < T) {
            int k0 = (t + 1) * 16;
            av0 = aok ? *(const float4*)(aptr + k0 + 0) : make_float4(0.f, 0.f, 0.f, 0.f);
            av1 = aok ? *(const float4*)(aptr + k0 + 4) : make_float4(0.f, 0.f, 0.f, 0.f);
            bv = *(const float4*)&B[(size_t)(k0 + bbr) * N + bn + bc4];
        }
#pragma unroll
        for (int k = 0; k < 16; k++) {
            U4 a0, b0, b1;
            a0.f = *(const float4*)&As[buf][k][tm * 4];
            b0.f = *(const float4*)&Bs[buf][k][tn * 4];
            b1.f = *(const float4*)&Bs[buf][k][tn * 4 + 32];
            ull bp[4] = {b0.p[0], b0.p[1], b1.p[0], b1.p[1]};
            float a[4] = {a0.f.x, a0.f.y, a0.f.z, a0.f.w};
#pragma unroll
            for (int i = 0; i < 4; i++) {
                ull ad = dupf(a[i]);
#pragma unroll
                for (int jp = 0; jp < 4; jp++) ffma2(accP[i][jp], ad, bp[jp]);
            }
        }
        // single sync per iter: next store targets buf^1, whose last read was
        // iter t-1, separated by this iter's sync above.
    }

    // unpack
    float acc[4][8];
#pragma unroll
    for (int i = 0; i < 4; i++)
#pragma unroll
        for (int jp = 0; jp < 4; jp++) {
            U2 u; u.p = accP[i][jp];
            int j0 = (jp < 2) ? jp * 2 : 4 + (jp - 2) * 2;
            acc[i][j0] = u.f.x;
            acc[i][j0 + 1] = u.f.y;
        }

    // epilogue
    float elp[4], erp[4], alv[8], arv[8], bvv[8];
    const int head = blockIdx.y;
    if (al) {
#pragma unroll
        for (int j = 0; j < 8; j++) {
            int c = tn * 4 + ((j < 4) ? j : 32 + (j - 4));
            alv[j] = __ldg(&al[head * 64 + c]);
            arv[j] = __ldg(&ar[head * 64 + c]);
        }
#pragma unroll
        for (int i = 0; i < 4; i++) { elp[i] = 0.f; erp[i] = 0.f; }
    }
    if (bias) {
#pragma unroll
        for (int j = 0; j < 8; j++) {
            int c = tn * 4 + ((j < 4) ? j : 32 + (j - 4));
            bvv[j] = __ldg(&bias[bn + c]);
        }
    }
#pragma unroll
    for (int i = 0; i < 4; i++) {
        int gr = bm + tm * 4 + i;
        float v[8];
#pragma unroll
        for (int j = 0; j < 8; j++) {
            float t = acc[i][j];
            if (bias) t += bvv[j];
            if (act) t = fmaxf(t, 0.f);
            v[j] = t;
            if (al) { elp[i] += t * alv[j]; erp[i] += t * arv[j]; }
        }
        if (gr < M) {
            float* cp = C + (size_t)gr * N + bn;
            *(float4*)(cp + tn * 4)      = make_float4(v[0], v[1], v[2], v[3]);
            *(float4*)(cp + tn * 4 + 32) = make_float4(v[4], v[5], v[6], v[7]);
        }
    }
    if (al) {
#pragma unroll
        for (int off = 1; off < 8; off <<= 1) {
#pragma unroll
            for (int i = 0; i < 4; i++) {
                elp[i] += __shfl_xor_sync(0xFFFFFFFFu, elp[i], off);
                erp[i] += __shfl_xor_sync(0xFFFFFFFFu, erp[i], off);
            }
        }
        if (tn == 0) {
#pragma unroll
            for (int i = 0; i < 4; i++) {
                int gr = bm + tm * 4 + i;
                if (gr < M) {
                    g_el[gr * 3 + head] = elp[i];
                    g_er[gr * 3 + head] = erp[i];
                }
            }
        }
    }
}

__device__ __forceinline__ float leaky(float x) { return x > 0.f ? x : NEG_SLOPE * x; }

// ---------------- per-dst max (one warp per node) ----------------
__global__ void max_k() {
    int warp = (blockIdx.x * blockDim.x + threadIdx.x) >> 5;
    int lane = threadIdx.x & 31;
    if (warp >= N_NODES) return;
    int beg = g_rowptr[warp], end = g_rowptr[warp + 1];
    float er0 = g_er[warp * 3 + 0];
    float er1 = g_er[warp * 3 + 1];
    float er2 = g_er[warp * 3 + 2];
    float m0 = -1e30f, m1 = -1e30f, m2 = -1e30f;
    for (int i = beg + lane; i < end; i += 32) {
        int s = g_srcs[i];
        m0 = fmaxf(m0, leaky(g_el[s * 3 + 0] + er0));
        m1 = fmaxf(m1, leaky(g_el[s * 3 + 1] + er1));
        m2 = fmaxf(m2, leaky(g_el[s * 3 + 2] + er2));
    }
#pragma unroll
    for (int off = 16; off; off >>= 1) {
        m0 = fmaxf(m0, __shfl_xor_sync(0xFFFFFFFFu, m0, off));
        m1 = fmaxf(m1, __shfl_xor_sync(0xFFFFFFFFu, m1, off));
        m2 = fmaxf(m2, __shfl_xor_sync(0xFFFFFFFFu, m2, off));
    }
    if (lane == 0) {
        g_m[warp * 3 + 0] = m0;
        g_m[warp * 3 + 1] = m1;
        g_m[warp * 3 + 2] = m2;
    }
}

// ---------------- per-edge softmax numerators ----------------
__global__ void wgt_k() {
    int e = blockIdx.x * blockDim.x + threadIdx.x;
    if (e >= N_EDGES) return;
    int s = g_srcs[e];
    int d = g_edst[e];
    float w0 = __expf(leaky(g_el[s * 3 + 0] + g_er[d * 3 + 0]) - g_m[d * 3 + 0]);
    float w1 = __expf(leaky(g_el[s * 3 + 1] + g_er[d * 3 + 1]) - g_m[d * 3 + 1]);
    float w2 = __expf(leaky(g_el[s * 3 + 2] + g_er[d * 3 + 2]) - g_m[d * 3 + 2]);
    *(float4*)&g_w[(size_t)e * 4] = make_float4(w0, w1, w2, 0.f);
}

// ---------------- aggregation: one warp per dst node ----------------
__global__ void agg_k(const float* __restrict__ feat, const float* __restrict__ bias,
                      float* __restrict__ out) {
    int warp = (blockIdx.x * blockDim.x + threadIdx.x) >> 5;
    int lane = threadIdx.x & 31;
    if (warp >= N_NODES) return;
    int beg = g_rowptr[warp], end = g_rowptr[warp + 1];

    int base = lane * 6;
    int h0 = (base + 0) >> 6, h1 = (base + 1) >> 6, h2 = (base + 2) >> 6;
    int h3 = (base + 3) >> 6, h4 = (base + 4) >> 6, h5 = (base + 5) >> 6;
    float acc0 = 0.f, acc1 = 0.f, acc2 = 0.f, acc3 = 0.f, acc4 = 0.f, acc5 = 0.f;
    float s0 = 0.f, s1 = 0.f, s2 = 0.f;

    int sNext = 0;
    float4 wNext = make_float4(0.f, 0.f, 0.f, 0.f);
    if (beg < end) {
        sNext = g_srcs[beg];
        wNext = *(const float4*)&g_w[(size_t)beg * 4];
    }
    for (int i = beg; i < end; i++) {
        int s = sNext;
        float4 w = wNext;
        if (i + 1 < end) {
            sNext = g_srcs[i + 1];
            wNext = *(const float4*)&g_w[(size_t)(i + 1) * 4];
        }
        s0 += w.x; s1 += w.y; s2 += w.z;
        const float* fp = feat + (size_t)s * HD + base;
        float2 v0 = *(const float2*)(fp + 0);
        float2 v1 = *(const float2*)(fp + 2);
        float2 v2 = *(const float2*)(fp + 4);
        float wa0 = h0 == 0 ? w.x : (h0 == 1 ? w.y : w.z);
        float wa1 = h1 == 0 ? w.x : (h1 == 1 ? w.y : w.z);
        float wa2 = h2 == 0 ? w.x : (h2 == 1 ? w.y : w.z);
        float wa3 = h3 == 0 ? w.x : (h3 == 1 ? w.y : w.z);
        float wa4 = h4 == 0 ? w.x : (h4 == 1 ? w.y : w.z);
        float wa5 = h5 == 0 ? w.x : (h5 == 1 ? w.y : w.z);
        acc0 += wa0 * v0.x; acc1 += wa1 * v0.y;
        acc2 += wa2 * v1.x; acc3 += wa3 * v1.y;
        acc4 += wa4 * v2.x; acc5 += wa5 * v2.y;
    }
    float i0 = 0.f, i1 = 0.f, i2 = 0.f;
    if (end > beg) { i0 = 1.f / s0; i1 = 1.f / s1; i2 = 1.f / s2; }
    float ia0 = h0 == 0 ? i0 : (h0 == 1 ? i1 : i2);
    float ia1 = h1 == 0 ? i0 : (h1 == 1 ? i1 : i2);
    float ia2 = h2 == 0 ? i0 : (h2 == 1 ? i1 : i2);
    float ia3 = h3 == 0 ? i0 : (h3 == 1 ? i1 : i2);
    float ia4 = h4 == 0 ? i0 : (h4 == 1 ? i1 : i2);
    float ia5 = h5 == 0 ? i0 : (h5 == 1 ? i1 : i2);
    float* op = out + (size_t)warp * HD + base;
    op[0] = fmaxf(acc0 * ia0 + bias[base + 0], 0.f);
    op[1] = fmaxf(acc1 * ia1 + bias[base + 1], 0.f);
    op[2] = fmaxf(acc2 * ia2 + bias[base + 2], 0.f);
    op[3] = fmaxf(acc3 * ia3 + bias[base + 3], 0.f);
    op[4] = fmaxf(acc4 * ia4 + bias[base + 4], 0.f);
    op[5] = fmaxf(acc5 * ia5 + bias[base + 5], 0.f);
}

// ---------------- host launch ----------------
extern "C" void kernel_launch(void* const* d_in, const int* in_sizes, int n_in,
                              void* d_out, int out_size) {
    const float* features = (const float*)d_in[0];
    const int*   src      = (const int*)d_in[1];
    const int*   dst      = (const int*)d_in[2];
    const float* W1  = (const float*)d_in[3];
    const float* al1 = (const float*)d_in[4];
    const float* ar1 = (const float*)d_in[5];
    const float* b1  = (const float*)d_in[6];
    const float* W2  = (const float*)d_in[7];
    const float* al2 = (const float*)d_in[8];
    const float* ar2 = (const float*)d_in[9];
    const float* b2  = (const float*)d_in[10];
    const float* Wm1 = (const float*)d_in[11];
    const float* bm1 = (const float*)d_in[12];
    const float* Wm2 = (const float*)d_in[13];
    const float* bm2 = (const float*)d_in[14];
    float* out = (float*)d_out;

    float *feat, *x, *hid;
    int *cnt;
    cudaGetSymbolAddress((void**)&feat, g_feat);
    cudaGetSymbolAddress((void**)&x, g_x);
    cudaGetSymbolAddress((void**)&hid, g_hid);
    cudaGetSymbolAddress((void**)&cnt, g_cnt);

    const int EB = (N_EDGES + 255) / 256;
    const int WB = (N_NODES * 32 + 255) / 256;
    const int GM = (N_NODES + 127) / 128;

    cudaMemsetAsync(cnt, 0, N_NODES * sizeof(int));
    hist_k<<<EB, 256>>>(dst);
    scan_k<<<1, 1024>>>();
    cudaMemsetAsync(cnt, 0, N_NODES * sizeof(int));
    scatter_k<<<EB, 256>>>(src, dst);

    // ---- GAT layer 1 ----
    gemm_k<IN_FEATS><<<dim3(GM, 3), 256>>>(features, W1, feat, N_NODES, HD, nullptr, 0, al1, ar1);
    max_k<<<WB, 256>>>();
    wgt_k<<<EB, 256>>>();
    agg_k<<<WB, 256>>>(feat, b1, x);

    // ---- GAT layer 2 ----
    gemm_k<HD><<<dim3(GM, 3), 256>>>(x, W2, feat, N_NODES, HD, nullptr, 0, al2, ar2);
    max_k<<<WB, 256>>>();
    wgt_k<<<EB, 256>>>();
    agg_k<<<WB, 256>>>(feat, b2, x);

    // ---- MLP head ----
    gemm_k<HD><<<dim3(GM, 1), 256>>>(x, Wm1, hid, N_NODES, HID, bm1, 1, nullptr, nullptr);
    gemm_k<HID><<<dim3(GM, 1), 256>>>(hid, Wm2, out, N_NODES, OUT_FEATS, bm2, 0, nullptr, nullptr);
}

// round 17
// speedup vs baseline: 1.0031x; 1.0007x over previous
#include <cuda_runtime.h>
#include <cuda_bf16.h>
#include <math.h>

#define N_NODES   50000
#define N_EDGES   800000
#define IN_FEATS  256
#define HID       64
#define HEADS     3
#define HD        192   // HEADS*HID
#define OUT_FEATS 64
#define NEG_SLOPE 0.2f

typedef unsigned long long ull;

// ---------------- device scratch (no allocs allowed) ----------------
__device__ float g_feat[(size_t)N_NODES * HD];
__device__ float g_x[(size_t)N_NODES * HD];
__device__ float g_hid[(size_t)N_NODES * HID];
__device__ float g_el[(size_t)N_NODES * HEADS];
__device__ float g_er[(size_t)N_NODES * HEADS];
__device__ float g_m[(size_t)N_NODES * HEADS];
__device__ float g_w[(size_t)N_EDGES * 4];       // per-edge softmax numerators (padded)
__device__ int   g_rowptr[N_NODES + 1];
__device__ int   g_cnt[N_NODES];
__device__ int   g_srcs[N_EDGES];                // src ids in CSR (dst-grouped) order
__device__ int   g_edst[N_EDGES];                // dst id per CSR slot

// ---------------- CSR build ----------------
__global__ void hist_k(const int* __restrict__ dst) {
    int e = blockIdx.x * blockDim.x + threadIdx.x;
    if (e < N_EDGES) atomicAdd(&g_cnt[dst[e]], 1);
}

__global__ void scan_k() {
    __shared__ int part[1024];
    int t = threadIdx.x;
    const int chunk = (N_NODES + 1023) / 1024;
    int beg = t * chunk;
    int end = min(beg + chunk, N_NODES);
    int s = 0;
    for (int i = beg; i < end; i++) s += g_cnt[i];
    part[t] = s;
    __syncthreads();
    for (int off = 1; off < 1024; off <<= 1) {
        int v = 0;
        if (t >= off) v = part[t - off];
        __syncthreads();
        part[t] += v;
        __syncthreads();
    }
    int run = (t == 0) ? 0 : part[t - 1];
    for (int i = beg; i < end; i++) { g_rowptr[i] = run; run += g_cnt[i]; }
    if (t == 1023) g_rowptr[N_NODES] = part[1023];
}

__global__ void scatter_k(const int* __restrict__ src, const int* __restrict__ dst) {
    int e = blockIdx.x * blockDim.x + threadIdx.x;
    if (e < N_EDGES) {
        int d = dst[e];
        int pos = atomicAdd(&g_cnt[d], 1);
        int slot = g_rowptr[d] + pos;
        g_srcs[slot] = src[e];
        g_edst[slot] = d;
    }
}

// ---------------- packed-f32x2 SGEMM 128x64 tile, 4x8 microtile, 256 threads --
union U4 { float4 f; ull p[2]; };
union U2 { ull p; float2 f; };

__device__ __forceinline__ ull dupf(float a) {
    ull r;
    asm("mov.b64 %0, {%1, %1};" : "=l"(r) : "f"(a));
    return r;
}
__device__ __forceinline__ void ffma2(ull& d, ull a, ull b) {
    asm("fma.rn.f32x2 %0, %1, %2, %0;" : "+l"(d) : "l"(a), "l"(b));
}

// C[M,N] = A[M,K] @ B[K,N] (+bias)(+relu). BN=64 per blockIdx.y.
// If al != null: also write g_el/g_er for head = blockIdx.y.
template<int K>
__global__ void __launch_bounds__(256)
gemm_k(const float* __restrict__ A, const float* __restrict__ B,
       float* __restrict__ C, int M, int N,
       const float* __restrict__ bias, int act,
       const float* __restrict__ al, const float* __restrict__ ar) {
    __shared__ float As[2][16][128];   // [buf][k][m]
    __shared__ float Bs[2][16][64];    // [buf][k][n]
    const int tid = threadIdx.x;
    const int tm = tid >> 3;        // 0..31 (4 rows each)
    const int tn = tid & 7;         // 0..7  (8 cols each, split 4+4)
    const int bm = blockIdx.x * 128;
    const int bn = blockIdx.y * 64;

    ull accP[4][4];
#pragma unroll
    for (int i = 0; i < 4; i++)
#pragma unroll
        for (int j = 0; j < 4; j++) accP[i][j] = 0ull;

    // A: each thread loads 2 float4 of one row (row = tid>>1, k-half = tid&1)
    const int arow = tid >> 1;
    const int ahalf = tid & 1;
    const float* aptr = A + (size_t)(bm + arow) * K + ahalf * 8;
    const bool aok = (bm + arow) < M;
    // B: one float4 per thread
    const int bbr = tid >> 4, bc4 = (tid & 15) << 2;

    float4 av0, av1, bv;
    av0 = aok ? *(const float4*)(aptr + 0) : make_float4(0.f, 0.f, 0.f, 0.f);
    av1 = aok ? *(const float4*)(aptr + 4) : make_float4(0.f, 0.f, 0.f, 0.f);
    bv = *(const float4*)&B[(size_t)bbr * N + bn + bc4];

    const int T = K / 16;
#pragma unroll 1
    for (int t = 0; t < T; t++) {
        const int buf = t & 1;
        As[buf][ahalf * 8 + 0][arow] = av0.x;
        As[buf][ahalf * 8 + 1][arow] = av0.y;
        As[buf][ahalf * 8 + 2][arow] = av0.z;
        As[buf][ahalf * 8 + 3][arow] = av0.w;
        As[buf][ahalf * 8 + 4][arow] = av1.x;
        As[buf][ahalf * 8 + 5][arow] = av1.y;
        As[buf][ahalf * 8 + 6][arow] = av1.z;
        As[buf][ahalf * 8 + 7][arow] = av1.w;
        *(float4*)&Bs[buf][bbr][bc4] = bv;
        __syncthreads();
        if (t + 1 < T) {
            int k0 = (t + 1) * 16;
            av0 = aok ? *(const float4*)(aptr + k0 + 0) : make_float4(0.f, 0.f, 0.f, 0.f);
            av1 = aok ? *(const float4*)(aptr + k0 + 4) : make_float4(0.f, 0.f, 0.f, 0.f);
            bv = *(const float4*)&B[(size_t)(k0 + bbr) * N + bn + bc4];
        }
#pragma unroll
        for (int k = 0; k < 16; k++) {
            U4 a0, b0, b1;
            a0.f = *(const float4*)&As[buf][k][tm * 4];
            b0.f = *(const float4*)&Bs[buf][k][tn * 4];
            b1.f = *(const float4*)&Bs[buf][k][tn * 4 + 32];
            ull bp[4] = {b0.p[0], b0.p[1], b1.p[0], b1.p[1]};
            float a[4] = {a0.f.x, a0.f.y, a0.f.z, a0.f.w};
#pragma unroll
            for (int i = 0; i < 4; i++) {
                ull ad = dupf(a[i]);
#pragma unroll
                for (int jp = 0; jp < 4; jp++) ffma2(accP[i][jp], ad, bp[jp]);
            }
        }
        // single sync per iter: next store targets buf^1, whose last read was
        // iter t-1, separated by this iter's sync above.
    }

    // unpack
    float acc[4][8];
#pragma unroll
    for (int i = 0; i < 4; i++)
#pragma unroll
        for (int jp = 0; jp < 4; jp++) {
            U2 u; u.p = accP[i][jp];
            int j0 = (jp < 2) ? jp * 2 : 4 + (jp - 2) * 2;
            acc[i][j0] = u.f.x;
            acc[i][j0 + 1] = u.f.y;
        }

    // epilogue
    float elp[4], erp[4], alv[8], arv[8], bvv[8];
    const int head = blockIdx.y;
    if (al) {
#pragma unroll
        for (int j = 0; j < 8; j++) {
            int c = tn * 4 + ((j < 4) ? j : 32 + (j - 4));
            alv[j] = __ldg(&al[head * 64 + c]);
            arv[j] = __ldg(&ar[head * 64 + c]);
        }
#pragma unroll
        for (int i = 0; i < 4; i++) { elp[i] = 0.f; erp[i] = 0.f; }
    }
    if (bias) {
#pragma unroll
        for (int j = 0; j < 8; j++) {
            int c = tn * 4 + ((j < 4) ? j : 32 + (j - 4));
            bvv[j] = __ldg(&bias[bn + c]);
        }
    }
#pragma unroll
    for (int i = 0; i < 4; i++) {
        int gr = bm + tm * 4 + i;
        float v[8];
#pragma unroll
        for (int j = 0; j < 8; j++) {
            float t = acc[i][j];
            if (bias) t += bvv[j];
            if (act) t = fmaxf(t, 0.f);
            v[j] = t;
            if (al) { elp[i] += t * alv[j]; erp[i] += t * arv[j]; }
        }
        if (gr < M) {
            float* cp = C + (size_t)gr * N + bn;
            *(float4*)(cp + tn * 4)      = make_float4(v[0], v[1], v[2], v[3]);
            *(float4*)(cp + tn * 4 + 32) = make_float4(v[4], v[5], v[6], v[7]);
        }
    }
    if (al) {
#pragma unroll
        for (int off = 1; off < 8; off <<= 1) {
#pragma unroll
            for (int i = 0; i < 4; i++) {
                elp[i] += __shfl_xor_sync(0xFFFFFFFFu, elp[i], off);
                erp[i] += __shfl_xor_sync(0xFFFFFFFFu, erp[i], off);
            }
        }
        if (tn == 0) {
#pragma unroll
            for (int i = 0; i < 4; i++) {
                int gr = bm + tm * 4 + i;
                if (gr < M) {
                    g_el[gr * 3 + head] = elp[i];
                    g_er[gr * 3 + head] = erp[i];
                }
            }
        }
    }
}

__device__ __forceinline__ float leaky(float x) { return x > 0.f ? x : NEG_SLOPE * x; }

// ---------------- per-dst max (one warp per node) ----------------
__global__ void max_k() {
    int warp = (blockIdx.x * blockDim.x + threadIdx.x) >> 5;
    int lane = threadIdx.x & 31;
    if (warp >= N_NODES) return;
    int beg = g_rowptr[warp], end = g_rowptr[warp + 1];
    float er0 = g_er[warp * 3 + 0];
    float er1 = g_er[warp * 3 + 1];
    float er2 = g_er[warp * 3 + 2];
    float m0 = -1e30f, m1 = -1e30f, m2 = -1e30f;
    for (int i = beg + lane; i < end; i += 32) {
        int s = g_srcs[i];
        m0 = fmaxf(m0, leaky(g_el[s * 3 + 0] + er0));
        m1 = fmaxf(m1, leaky(g_el[s * 3 + 1] + er1));
        m2 = fmaxf(m2, leaky(g_el[s * 3 + 2] + er2));
    }
#pragma unroll
    for (int off = 16; off; off >>= 1) {
        m0 = fmaxf(m0, __shfl_xor_sync(0xFFFFFFFFu, m0, off));
        m1 = fmaxf(m1, __shfl_xor_sync(0xFFFFFFFFu, m1, off));
        m2 = fmaxf(m2, __shfl_xor_sync(0xFFFFFFFFu, m2, off));
    }
    if (lane == 0) {
        g_m[warp * 3 + 0] = m0;
        g_m[warp * 3 + 1] = m1;
        g_m[warp * 3 + 2] = m2;
    }
}

// ---------------- per-edge softmax numerators ----------------
__global__ void wgt_k() {
    int e = blockIdx.x * blockDim.x + threadIdx.x;
    if (e >= N_EDGES) return;
    int s = g_srcs[e];
    int d = g_edst[e];
    float w0 = __expf(leaky(g_el[s * 3 + 0] + g_er[d * 3 + 0]) - g_m[d * 3 + 0]);
    float w1 = __expf(leaky(g_el[s * 3 + 1] + g_er[d * 3 + 1]) - g_m[d * 3 + 1]);
    float w2 = __expf(leaky(g_el[s * 3 + 2] + g_er[d * 3 + 2]) - g_m[d * 3 + 2]);
    *(float4*)&g_w[(size_t)e * 4] = make_float4(w0, w1, w2, 0.f);
}

// ---------------- aggregation: one warp per dst node ----------------
__global__ void agg_k(const float* __restrict__ feat, const float* __restrict__ bias,
                      float* __restrict__ out) {
    int warp = (blockIdx.x * blockDim.x + threadIdx.x) >> 5;
    int lane = threadIdx.x & 31;
    if (warp >= N_NODES) return;
    int beg = g_rowptr[warp], end = g_rowptr[warp + 1];

    int base = lane * 6;
    int h0 = (base + 0) >> 6, h1 = (base + 1) >> 6, h2 = (base + 2) >> 6;
    int h3 = (base + 3) >> 6, h4 = (base + 4) >> 6, h5 = (base + 5) >> 6;
    float acc0 = 0.f, acc1 = 0.f, acc2 = 0.f, acc3 = 0.f, acc4 = 0.f, acc5 = 0.f;
    float s0 = 0.f, s1 = 0.f, s2 = 0.f;

    int sNext = 0;
    float4 wNext = make_float4(0.f, 0.f, 0.f, 0.f);
    if (beg < end) {
        sNext = g_srcs[beg];
        wNext = *(const float4*)&g_w[(size_t)beg * 4];
    }
    for (int i = beg; i < end; i++) {
        int s = sNext;
        float4 w = wNext;
        if (i + 1 < end) {
            sNext = g_srcs[i + 1];
            wNext = *(const float4*)&g_w[(size_t)(i + 1) * 4];
        }
        s0 += w.x; s1 += w.y; s2 += w.z;
        const float* fp = feat + (size_t)s * HD + base;
        float2 v0 = *(const float2*)(fp + 0);
        float2 v1 = *(const float2*)(fp + 2);
        float2 v2 = *(const float2*)(fp + 4);
        float wa0 = h0 == 0 ? w.x : (h0 == 1 ? w.y : w.z);
        float wa1 = h1 == 0 ? w.x : (h1 == 1 ? w.y : w.z);
        float wa2 = h2 == 0 ? w.x : (h2 == 1 ? w.y : w.z);
        float wa3 = h3 == 0 ? w.x : (h3 == 1 ? w.y : w.z);
        float wa4 = h4 == 0 ? w.x : (h4 == 1 ? w.y : w.z);
        float wa5 = h5 == 0 ? w.x : (h5 == 1 ? w.y : w.z);
        acc0 += wa0 * v0.x; acc1 += wa1 * v0.y;
        acc2 += wa2 * v1.x; acc3 += wa3 * v1.y;
        acc4 += wa4 * v2.x; acc5 += wa5 * v2.y;
    }
    float i0 = 0.f, i1 = 0.f, i2 = 0.f;
    if (end > beg) { i0 = 1.f / s0; i1 = 1.f / s1; i2 = 1.f / s2; }
    float ia0 = h0 == 0 ? i0 : (h0 == 1 ? i1 : i2);
    float ia1 = h1 == 0 ? i0 : (h1 == 1 ? i1 : i2);
    float ia2 = h2 == 0 ? i0 : (h2 == 1 ? i1 : i2);
    float ia3 = h3 == 0 ? i0 : (h3 == 1 ? i1 : i2);
    float ia4 = h4 == 0 ? i0 : (h4 == 1 ? i1 : i2);
    float ia5 = h5 == 0 ? i0 : (h5 == 1 ? i1 : i2);
    float* op = out + (size_t)warp * HD + base;
    op[0] = fmaxf(acc0 * ia0 + bias[base + 0], 0.f);
    op[1] = fmaxf(acc1 * ia1 + bias[base + 1], 0.f);
    op[2] = fmaxf(acc2 * ia2 + bias[base + 2], 0.f);
    op[3] = fmaxf(acc3 * ia3 + bias[base + 3], 0.f);
    op[4] = fmaxf(acc4 * ia4 + bias[base + 4], 0.f);
    op[5] = fmaxf(acc5 * ia5 + bias[base + 5], 0.f);
}

// ---------------- host launch ----------------
extern "C" void kernel_launch(void* const* d_in, const int* in_sizes, int n_in,
                              void* d_out, int out_size) {
    const float* features = (const float*)d_in[0];
    const int*   src      = (const int*)d_in[1];
    const int*   dst      = (const int*)d_in[2];
    const float* W1  = (const float*)d_in[3];
    const float* al1 = (const float*)d_in[4];
    const float* ar1 = (const float*)d_in[5];
    const float* b1  = (const float*)d_in[6];
    const float* W2  = (const float*)d_in[7];
    const float* al2 = (const float*)d_in[8];
    const float* ar2 = (const float*)d_in[9];
    const float* b2  = (const float*)d_in[10];
    const float* Wm1 = (const float*)d_in[11];
    const float* bm1 = (const float*)d_in[12];
    const float* Wm2 = (const float*)d_in[13];
    const float* bm2 = (const float*)d_in[14];
    float* out = (float*)d_out;

    float *feat, *x, *hid;
    int *cnt;
    cudaGetSymbolAddress((void**)&feat, g_feat);
    cudaGetSymbolAddress((void**)&x, g_x);
    cudaGetSymbolAddress((void**)&hid, g_hid);
    cudaGetSymbolAddress((void**)&cnt, g_cnt);

    const int EB = (N_EDGES + 255) / 256;
    const int WB = (N_NODES * 32 + 255) / 256;
    const int GM = (N_NODES + 127) / 128;

    cudaMemsetAsync(cnt, 0, N_NODES * sizeof(int));
    hist_k<<<EB, 256>>>(dst);
    scan_k<<<1, 1024>>>();
    cudaMemsetAsync(cnt, 0, N_NODES * sizeof(int));
    scatter_k<<<EB, 256>>>(src, dst);

    // ---- GAT layer 1 ----
    gemm_k<IN_FEATS><<<dim3(GM, 3), 256>>>(features, W1, feat, N_NODES, HD, nullptr, 0, al1, ar1);
    max_k<<<WB, 256>>>();
    wgt_k<<<EB, 256>>>();
    agg_k<<<WB, 256>>>(feat, b1, x);

    // ---- GAT layer 2 ----
    gemm_k<HD><<<dim3(GM, 3), 256>>>(x, W2, feat, N_NODES, HD, nullptr, 0, al2, ar2);
    max_k<<<WB, 256>>>();
    wgt_k<<<EB, 256>>>();
    agg_k<<<WB, 256>>>(feat, b2, x);

    // ---- MLP head ----
    gemm_k<HD><<<dim3(GM, 1), 256>>>(x, Wm1, hid, N_NODES, HID, bm1, 1, nullptr, nullptr);
    gemm_k<HID><<<dim3(GM, 1), 256>>>(hid, Wm2, out, N_NODES, OUT_FEATS, bm2, 0, nullptr, nullptr);
}